// round 15
// baseline (speedup 1.0000x reference)
#include <cuda_runtime.h>
#include <cuda_fp16.h>

#define BB 32
#define LL 1024
#define HH 1280
#define PP 128
#define NROWS (BB * LL)
#define INVT 14.285714285714286f
#define C1F (14.285714285714286f * 1.4426950408889634f)

// ---------------------------------------------------------------------------
// Helpers
// ---------------------------------------------------------------------------
__device__ __forceinline__ unsigned smem_to_u32(const void* p) {
    unsigned a;
    asm("{ .reg .u64 t; cvta.to.shared.u64 t, %1; cvt.u32.u64 %0, t; }" : "=r"(a) : "l"(p));
    return a;
}
static __device__ __forceinline__ unsigned sw128(unsigned off) {
    return off ^ ((off >> 3) & 0x70);
}
__device__ __forceinline__ float ex2f(float x) {
    float r;
    asm("ex2.approx.f32 %0, %1;" : "=f"(r) : "f"(x));
    return r;
}
__device__ __forceinline__ unsigned f16pack(float lo, float hi) {
    unsigned r;
    asm("cvt.rn.f16x2.f32 %0, %1, %2;" : "=r"(r) : "f"(hi), "f"(lo));
    return r;
}

#define LDSM4(r0, r1, r2, r3, addr)                                          \
    asm volatile("ldmatrix.sync.aligned.m8n8.x4.shared.b16 {%0,%1,%2,%3}, [%4];" \
                 : "=r"(r0), "=r"(r1), "=r"(r2), "=r"(r3) : "r"(addr))

#define MMA(d, a, b)                                                         \
    asm volatile("mma.sync.aligned.m16n8k16.row.col.f32.f16.f16.f32 "        \
                 "{%0,%1,%2,%3},{%4,%5,%6,%7},{%8,%9},{%0,%1,%2,%3};"        \
                 : "+f"((d)[0]), "+f"((d)[1]), "+f"((d)[2]), "+f"((d)[3])    \
                 : "r"((a)[0]), "r"((a)[1]), "r"((a)[2]), "r"((a)[3]),       \
                   "r"((b)[0]), "r"((b)[1]))

#define CP16(dst, src) \
    asm volatile("cp.async.cg.shared.global [%0], [%1], 16;" :: "r"(dst), "l"(src))
#define CP_COMMIT() asm volatile("cp.async.commit_group;" ::: "memory")
#define CP_WAIT0()  asm volatile("cp.async.wait_group 0;" ::: "memory")

// ---------------------------------------------------------------------------
// Device scratch
// ---------------------------------------------------------------------------
__device__ __align__(16) __half g_emb[NROWS * PP];
__device__ __align__(16) __half g_wt[PP * HH];   // [n][k] K-major
__device__ __align__(16) float g_se[NROWS];
__device__ __align__(16) float g_sp[NROWS];
__device__ int g_cnt4[BB * 4];
__device__ int g_cm[BB];
__device__ int g_cv[BB];
__device__ float g_loss[BB];
__device__ int g_ok[BB];
__device__ int g_bdone[BB];
__device__ int g_done2 = 0;

// ---------------------------------------------------------------------------
// Kernel 0: W -> fp16 [n][k] via smem transpose (10 blocks only)
// ---------------------------------------------------------------------------
__global__ __launch_bounds__(256) void kern_wt(const float* __restrict__ W) {
    const int tid = threadIdx.x;
    __shared__ unsigned short smT[128 * 136];
    const int k0 = blockIdx.x * 128;
#pragma unroll
    for (int i = 0; i < 16; i++) {
        int u = i * 256 + tid;
        int row = u >> 5, c4 = u & 31;
        float4 v = *(const float4*)(W + (size_t)(k0 + row) * PP + c4 * 4);
        *(unsigned*)&smT[row * 136 + c4 * 4] = f16pack(v.x, v.y);
        *(unsigned*)&smT[row * 136 + c4 * 4 + 2] = f16pack(v.z, v.w);
    }
    __syncthreads();
#pragma unroll
    for (int i = 0; i < 8; i++) {
        int u = i * 256 + tid;
        int nn = (u >> 4) & 127;
        int kg = (u & 15);
        unsigned short h[8];
#pragma unroll
        for (int j = 0; j < 8; j++) h[j] = smT[(kg * 8 + j) * 136 + nn];
        uint4 o;
        o.x = (unsigned)h[0] | ((unsigned)h[1] << 16);
        o.y = (unsigned)h[2] | ((unsigned)h[3] << 16);
        o.z = (unsigned)h[4] | ((unsigned)h[5] << 16);
        o.w = (unsigned)h[6] | ((unsigned)h[7] << 16);
        *(uint4*)(g_wt + (size_t)nn * HH + k0 + kg * 8) = o;
    }
}

// ---------------------------------------------------------------------------
// Kernel 1: proj + L2-normalize; invalid rows ZERO; also zeroes accumulators
// ---------------------------------------------------------------------------
#define P_A(b) (2048 + (b) * 16384)
#define P_B(b) (34816 + (b) * 16384)
#define PROJ_SMEM 67584

__global__ __launch_bounds__(256, 2)
void kern_proj(const float* __restrict__ hid, const float* __restrict__ bias,
               const int* __restrict__ amask, const int* __restrict__ labels) {
    extern __shared__ char sm[];
    const unsigned sb = smem_to_u32(sm);
    const int tid = threadIdx.x, lane = tid & 31, wid = tid >> 5;
    const int wm = wid & 3, wn = wid >> 2;
    const int m0 = wm * 32, n0 = wn * 64;
    const int row0 = blockIdx.x * 128;
    float* bias_s = (float*)sm;
    float* ssbuf = (float*)(sm + 512);

    // zero stat accumulators (grid covers 65536 threads; NROWS=32768)
    {
        int gt = blockIdx.x * 256 + tid;
        if (gt < NROWS) { g_se[gt] = 0.f; g_sp[gt] = 0.f; }
        else {
            int g2 = gt - NROWS;
            if (g2 < BB * 4) g_cnt4[g2] = 0;
            else if (g2 < BB * 4 + BB) g_cm[g2 - BB * 4] = 0;
            else if (g2 < BB * 4 + 2 * BB) g_cv[g2 - BB * 4 - BB] = 0;
            else if (g2 < BB * 4 + 3 * BB) g_bdone[g2 - BB * 4 - 2 * BB] = 0;
        }
    }

    if (tid < 128) bias_s[tid] = bias[tid];

    unsigned swxA[2], swxB[4];
#pragma unroll
    for (int mt = 0; mt < 2; mt++) {
        unsigned r = m0 + mt * 16 + (lane & 15);
        swxA[mt] = sw128(r * 128 + ((lane >> 4) << 4));
    }
    {
        unsigned q = lane >> 3;
#pragma unroll
        for (int p = 0; p < 4; p++) {
            unsigned nr = n0 + p * 16 + ((q >> 1) << 3) + (lane & 7);
            swxB[p] = sw128(nr * 128 + ((q & 1) << 4));
        }
    }

    float acc[2][8][4];
#pragma unroll
    for (int mt = 0; mt < 2; mt++)
#pragma unroll
        for (int nt = 0; nt < 8; nt++)
#pragma unroll
            for (int e = 0; e < 4; e++) acc[mt][nt][e] = 0.f;

#pragma unroll
    for (int i = 0; i < 4; i++) {
        int u = i * 256 + tid;
        int n = u >> 3, k8 = u & 7;
        CP16(sb + P_B(0) + sw128((unsigned)(n * 128 + k8 * 16)),
             g_wt + (size_t)n * HH + k8 * 8);
    }
    CP_COMMIT();
#pragma unroll
    for (int q = 0; q < 4; q++) {
        int u = q * 256 + tid;
        int row = u >> 3, k8 = u & 7;
        const float* s = hid + (size_t)(row0 + row) * HH + k8 * 8;
        float4 v0 = *(const float4*)s;
        float4 v1 = *(const float4*)(s + 4);
        uint4 ra = make_uint4(f16pack(v0.x, v0.y), f16pack(v0.z, v0.w),
                              f16pack(v1.x, v1.y), f16pack(v1.z, v1.w));
        *(uint4*)(sm + P_A(0) + sw128((unsigned)(row * 128 + k8 * 16))) = ra;
    }
    CP_WAIT0();
    __syncthreads();

#pragma unroll 1
    for (int c = 0; c < 20; c++) {
        const int buf = c & 1;
        float4 va[8];
        if (c < 19) {
            const int k0n = (c + 1) * 64;
#pragma unroll
            for (int q = 0; q < 4; q++) {
                int u = q * 256 + tid;
                int row = u >> 3, k8 = u & 7;
                const float* s = hid + (size_t)(row0 + row) * HH + k0n + k8 * 8;
                va[2 * q] = *(const float4*)s;
                va[2 * q + 1] = *(const float4*)(s + 4);
            }
#pragma unroll
            for (int i = 0; i < 4; i++) {
                int u = i * 256 + tid;
                int n = u >> 3, k8 = u & 7;
                CP16(sb + P_B(buf ^ 1) + sw128((unsigned)(n * 128 + k8 * 16)),
                     g_wt + (size_t)n * HH + k0n + k8 * 8);
            }
            CP_COMMIT();
        }

        const unsigned a_base = sb + P_A(buf);
        const unsigned b_base = sb + P_B(buf);
#pragma unroll
        for (int kk = 0; kk < 4; kk++) {
            const unsigned kk2 = kk * 32;
            unsigned ah[2][4], bh[8][2];
#pragma unroll
            for (int mt = 0; mt < 2; mt++)
                LDSM4(ah[mt][0], ah[mt][1], ah[mt][2], ah[mt][3],
                      a_base + (swxA[mt] ^ kk2));
#pragma unroll
            for (int p = 0; p < 4; p++) {
                unsigned t0, t1, t2, t3;
                LDSM4(t0, t1, t2, t3, b_base + (swxB[p] ^ kk2));
                bh[2 * p][0] = t0; bh[2 * p][1] = t1;
                bh[2 * p + 1][0] = t2; bh[2 * p + 1][1] = t3;
            }
#pragma unroll
            for (int mt = 0; mt < 2; mt++)
#pragma unroll
                for (int nt = 0; nt < 8; nt++)
                    MMA(acc[mt][nt], ah[mt], bh[nt]);
        }

        if (c < 19) {
#pragma unroll
            for (int q = 0; q < 4; q++) {
                int u = q * 256 + tid;
                int row = u >> 3, k8 = u & 7;
                uint4 ra = make_uint4(
                    f16pack(va[2 * q].x, va[2 * q].y),
                    f16pack(va[2 * q].z, va[2 * q].w),
                    f16pack(va[2 * q + 1].x, va[2 * q + 1].y),
                    f16pack(va[2 * q + 1].z, va[2 * q + 1].w));
                *(uint4*)(sm + P_A(buf ^ 1) + sw128((unsigned)(row * 128 + k8 * 16))) = ra;
            }
            CP_WAIT0();
        }
        __syncthreads();
    }

    float ss[4] = {0.f, 0.f, 0.f, 0.f};
#pragma unroll
    for (int mt = 0; mt < 2; mt++)
#pragma unroll
        for (int nt = 0; nt < 8; nt++)
#pragma unroll
            for (int e = 0; e < 4; e++) {
                int s = e >> 1;
                int col = n0 + nt * 8 + (lane & 3) * 2 + (e & 1);
                float v = acc[mt][nt][e] + bias_s[col];
                acc[mt][nt][e] = v;
                ss[mt * 2 + s] += v * v;
            }
#pragma unroll
    for (int r2 = 0; r2 < 4; r2++) {
        ss[r2] += __shfl_xor_sync(0xffffffffu, ss[r2], 1);
        ss[r2] += __shfl_xor_sync(0xffffffffu, ss[r2], 2);
    }
    if ((lane & 3) == 0) {
#pragma unroll
        for (int r2 = 0; r2 < 4; r2++) {
            int rowg = wm * 32 + (r2 >> 1) * 16 + (lane >> 2) + (r2 & 1) * 8;
            ssbuf[wn * 128 + rowg] = ss[r2];
        }
    }
    __syncthreads();
#pragma unroll
    for (int r2 = 0; r2 < 4; r2++) {
        int mt = r2 >> 1, s = r2 & 1;
        int rowg = wm * 32 + mt * 16 + (lane >> 2) + s * 8;
        int gr = row0 + rowg;
        int vv = (amask[gr] != 0) && (labels[gr] != -100);
        float tot = ssbuf[rowg] + ssbuf[128 + rowg];
        float inv = rsqrtf(tot);
        inv = inv * (1.5f - 0.5f * tot * inv * inv);
        if (!vv) inv = 0.f;
        __half* oh = g_emb + (size_t)gr * PP;
#pragma unroll
        for (int nt = 0; nt < 8; nt++) {
            int col = n0 + nt * 8 + (lane & 3) * 2;
            *(unsigned*)(oh + col) =
                f16pack(acc[mt][nt][s * 2] * inv, acc[mt][nt][s * 2 + 1] * inv);
        }
    }
}

// ---------------------------------------------------------------------------
// Kernel 2: SYMMETRIC sim + per-batch last-CTA loss + global last-CTA scalar.
// Grid 32 x 36 upper-tri 128x128 blocks, 512 threads (16 warps 4m x 4n).
// ---------------------------------------------------------------------------
#define SMS_LABJ   0
#define SMS_POSM   512
#define SMS_ROWRED 1024
#define SMS_COLRED 5120
#define SMS_A      10240
#define SMS_B      43008
#define SIM_SMEM   75776

__global__ __launch_bounds__(512)
void kern_sim(const int* __restrict__ amask, const int* __restrict__ labels,
              float* __restrict__ out) {
    extern __shared__ char sm[];
    __shared__ int blast, glast;
    __shared__ float wpl[16];
    const unsigned sb = smem_to_u32(sm);
    const int tid = threadIdx.x, lane = tid & 31, wid = tid >> 5;
    const int wm = wid & 3, wn = wid >> 2;
    const int m0 = wm * 32, n0 = wn * 32;
    const int b = blockIdx.x / 36;
    int p = blockIdx.x % 36;
    int it = 0;
    while (p >= 8 - it) { p -= 8 - it; it++; }
    const int jt = it + p;
    const int diag = (it == jt);
    const int i0 = it * 128, j0 = jt * 128;
    const __half* eb = g_emb + (size_t)b * LL * PP;
    int* labjp = (int*)sm;
    unsigned* posm = (unsigned*)(sm + SMS_POSM);
    float* rowred = (float*)(sm + SMS_ROWRED);
    float* colred = (float*)(sm + SMS_COLRED);

#pragma unroll
    for (int i = 0; i < 4; i++) {
        int u = i * 512 + tid;
        int row = u >> 4, k8 = u & 15;
        unsigned off = (unsigned)((k8 >> 3) * 16384) +
                       sw128((unsigned)(row * 128 + (k8 & 7) * 16));
        CP16(sb + SMS_A + off, eb + (size_t)(i0 + row) * PP + k8 * 8);
    }
    if (!diag) {
#pragma unroll
        for (int i = 0; i < 4; i++) {
            int u = i * 512 + tid;
            int row = u >> 4, k8 = u & 15;
            unsigned off = (unsigned)((k8 >> 3) * 16384) +
                           sw128((unsigned)(row * 128 + (k8 & 7) * 16));
            CP16(sb + SMS_B + off, eb + (size_t)(j0 + row) * PP + k8 * 8);
        }
    }
    CP_COMMIT();

    if (tid < 128) {
        int mm = amask[b * LL + j0 + tid];
        int lb = labels[b * LL + j0 + tid];
        int vv = (mm != 0) && (lb != -100);
        labjp[tid] = lb;
#pragma unroll
        for (int l = 0; l < 4; l++) {
            unsigned pb = __ballot_sync(0xffffffffu, vv && (lb == l));
            if (lane == 0) {
                posm[l * 4 + wid] = pb;
                if (diag) atomicAdd(&g_cnt4[b * 4 + l], __popc(pb));
            }
        }
        if (diag) {
            unsigned mb = __ballot_sync(0xffffffffu, mm != 0);
            unsigned vb = __ballot_sync(0xffffffffu, vv);
            if (lane == 0) {
                atomicAdd(&g_cm[b], __popc(mb));
                atomicAdd(&g_cv[b], __popc(vb));
            }
        }
    }

    int labi_[4];
#pragma unroll
    for (int r2 = 0; r2 < 4; r2++) {
        int rowg = m0 + (r2 >> 1) * 16 + (lane >> 2) + (r2 & 1) * 8;
        int gi = b * LL + i0 + rowg;
        int lb = labels[gi];
        labi_[r2] = ((amask[gi] != 0) && (lb != -100)) ? lb : -1;
    }

    unsigned swxA[2], swxB[2];
#pragma unroll
    for (int mt = 0; mt < 2; mt++) {
        unsigned r = m0 + mt * 16 + (lane & 15);
        swxA[mt] = sw128(r * 128 + ((lane >> 4) << 4));
    }
    {
        unsigned q = lane >> 3;
#pragma unroll
        for (int pq = 0; pq < 2; pq++) {
            unsigned nr = n0 + pq * 16 + ((q >> 1) << 3) + (lane & 7);
            swxB[pq] = sw128(nr * 128 + ((q & 1) << 4));
        }
    }

    CP_WAIT0();
    __syncthreads();

    float acc[2][4][4];
#pragma unroll
    for (int mt = 0; mt < 2; mt++)
#pragma unroll
        for (int nt = 0; nt < 4; nt++)
#pragma unroll
            for (int e = 0; e < 4; e++) acc[mt][nt][e] = 0.f;

    const unsigned aT = sb + SMS_A;
    const unsigned bT = diag ? (sb + SMS_A) : (sb + SMS_B);
#pragma unroll
    for (int kk = 0; kk < 8; kk++) {
        const unsigned ch = (unsigned)((kk >> 2) * 16384);
        const unsigned kk2 = (kk & 3) * 32;
        unsigned ah[2][4], bh[4][2];
#pragma unroll
        for (int mt = 0; mt < 2; mt++)
            LDSM4(ah[mt][0], ah[mt][1], ah[mt][2], ah[mt][3],
                  aT + ch + (swxA[mt] ^ kk2));
#pragma unroll
        for (int pq = 0; pq < 2; pq++) {
            unsigned t0, t1, t2, t3;
            LDSM4(t0, t1, t2, t3, bT + ch + (swxB[pq] ^ kk2));
            bh[2 * pq][0] = t0; bh[2 * pq][1] = t1;
            bh[2 * pq + 1][0] = t2; bh[2 * pq + 1][1] = t3;
        }
#pragma unroll
        for (int mt = 0; mt < 2; mt++)
#pragma unroll
            for (int nt = 0; nt < 4; nt++)
                MMA(acc[mt][nt], ah[mt], bh[nt]);
    }

    // ---- epilogue ----
    const int sh = (lane & 3) * 2;
    float se_[4] = {0.f, 0.f, 0.f, 0.f}, sp_[4] = {0.f, 0.f, 0.f, 0.f};
    float colse[8], colsp[8];
    int lbjv[8];
#pragma unroll
    for (int idx = 0; idx < 8; idx++) { colse[idx] = 0.f; colsp[idx] = 0.f; }
    if (!diag) {
#pragma unroll
        for (int idx = 0; idx < 8; idx++)
            lbjv[idx] = labjp[n0 + (idx >> 1) * 8 + sh + (idx & 1)];
    }

#pragma unroll
    for (int r2 = 0; r2 < 4; r2++) {
        const int mt = r2 >> 1, s = r2 & 1;
        const int rowg = m0 + mt * 16 + (lane >> 2) + s * 8;
        const int labi = labi_[r2];
        unsigned pmr = (labi >= 0) ? posm[labi * 4 + wn] : 0u;
        if (diag) {
            const int selfhere = ((rowg >> 5) == wn);
            const int bps = rowg & 31;
            if (selfhere) pmr &= ~(1u << bps);
#pragma unroll
            for (int nt = 0; nt < 4; nt++)
#pragma unroll
                for (int cc = 0; cc < 2; cc++) {
                    int bp = nt * 8 + sh + cc;
                    float a = acc[mt][nt][s * 2 + cc];
                    float e = ex2f(fmaf(a, C1F, -C1F));
                    if (selfhere && bp == bps) e = 0.f;
                    se_[r2] += e;
                    if ((pmr >> bp) & 1) sp_[r2] += a;
                }
        } else {
#pragma unroll
            for (int nt = 0; nt < 4; nt++)
#pragma unroll
                for (int cc = 0; cc < 2; cc++) {
                    int idx = nt * 2 + cc;
                    int bp = nt * 8 + sh + cc;
                    float a = acc[mt][nt][s * 2 + cc];
                    float e = ex2f(fmaf(a, C1F, -C1F));
                    se_[r2] += e;
                    colse[idx] += e;
                    if ((pmr >> bp) & 1) sp_[r2] += a;
                    colsp[idx] += (labi == lbjv[idx]) ? a : 0.f;
                }
        }
    }

#pragma unroll
    for (int o = 1; o <= 2; o <<= 1)
#pragma unroll
        for (int r2 = 0; r2 < 4; r2++) {
            se_[r2] += __shfl_xor_sync(0xffffffffu, se_[r2], o);
            sp_[r2] += __shfl_xor_sync(0xffffffffu, sp_[r2], o);
        }
    if ((lane & 3) == 0) {
#pragma unroll
        for (int r2 = 0; r2 < 4; r2++) {
            int rowg = m0 + (r2 >> 1) * 16 + (lane >> 2) + (r2 & 1) * 8;
            rowred[(wn * 128 + rowg) * 2] = se_[r2];
            rowred[(wn * 128 + rowg) * 2 + 1] = sp_[r2];
        }
    }
    if (!diag) {
#pragma unroll
        for (int idx = 0; idx < 8; idx++)
#pragma unroll
            for (int o = 4; o <= 16; o <<= 1) {
                colse[idx] += __shfl_xor_sync(0xffffffffu, colse[idx], o);
                colsp[idx] += __shfl_xor_sync(0xffffffffu, colsp[idx], o);
            }
        if ((lane >> 2) == 0) {
#pragma unroll
            for (int idx = 0; idx < 8; idx++) {
                int col = n0 + (idx >> 1) * 8 + sh + (idx & 1);
                colred[(wm * 128 + col) * 2] = colse[idx];
                colred[(wm * 128 + col) * 2 + 1] = colsp[idx];
            }
        }
    }
    __syncthreads();

    if (tid < 256) {
        int row = tid >> 1, st = tid & 1;
        float v = rowred[row * 2 + st] + rowred[(128 + row) * 2 + st] +
                  rowred[(256 + row) * 2 + st] + rowred[(384 + row) * 2 + st];
        atomicAdd((st ? g_sp : g_se) + b * LL + i0 + row, v);
    } else if (!diag) {
        int u = tid - 256;
        int col = u >> 1, st = u & 1;
        float v = colred[col * 2 + st] + colred[(128 + col) * 2 + st] +
                  colred[(256 + col) * 2 + st] + colred[(384 + col) * 2 + st];
        atomicAdd((st ? g_sp : g_se) + b * LL + j0 + col, v);
    }

    // ---- per-batch last CTA: compute this batch's loss ----
    __threadfence();
    if (tid == 0) blast = (atomicAdd(&g_bdone[b], 1) == 35);
    __syncthreads();
    if (!blast) return;
    __threadfence();

    const int cv = __ldcg(&g_cv[b]);
    const int cm = __ldcg(&g_cm[b]);
    const float corr = (float)(LL - cv) * ex2f(-C1F);
    float al = 0.f;
#pragma unroll
    for (int q = 0; q < 2; q++) {
        int a = b * LL + q * 512 + tid;
        int lb = labels[a];
        if ((amask[a] != 0) && (lb != -100)) {
            float npf = (float)(__ldcg(&g_cnt4[b * 4 + lb]) - 1);
            if (npf > 0.f) {
                float sec = fmaxf(__ldcg(&g_se[a]) - corr, 0.f) + 1e-12f;
                al += (INVT * __ldcg(&g_sp[a]) - npf * (INVT + __logf(sec))) / npf;
            }
        }
    }
#pragma unroll
    for (int o = 16; o >= 1; o >>= 1) al += __shfl_xor_sync(0xffffffffu, al, o);
    if (lane == 0) wpl[wid] = al;
    __syncthreads();
    if (tid == 0) {
        float s = 0.f;
#pragma unroll
        for (int w = 0; w < 16; w++) s += wpl[w];
        int ok = (cm >= 2);
        g_loss[b] = ok ? (-s / (float)(cv >= 1 ? cv : 1)) : 0.f;
        g_ok[b] = ok;
        g_bdone[b] = 0;   // reset for next replay
    }

    // ---- global last batch: final scalar ----
    __threadfence();
    if (tid == 0) glast = (atomicAdd(&g_done2, 1) == BB - 1);
    __syncthreads();
    if (glast) {
        __threadfence();
        if (tid < 32) {
            float lossb = __ldcg(&g_loss[tid]);
            int ns = __ldcg(&g_ok[tid]);
#pragma unroll
            for (int o = 16; o >= 1; o >>= 1) {
                lossb += __shfl_xor_sync(0xffffffffu, lossb, o);
                ns += __shfl_xor_sync(0xffffffffu, ns, o);
            }
            if (tid == 0) {
                out[0] = lossb / (float)(ns > 0 ? ns : 1);
                g_done2 = 0;
            }
        }
    }
}

// ---------------------------------------------------------------------------
extern "C" void kernel_launch(void* const* d_in, const int* in_sizes, int n_in,
                              void* d_out, int out_size) {
    const float* hid = (const float*)d_in[0];
    const float* W = (const float*)d_in[1];
    const float* bias = (const float*)d_in[2];
    const int* amask = (const int*)d_in[3];
    const int* labels = (const int*)d_in[4];
    float* out = (float*)d_out;

    cudaFuncSetAttribute(kern_proj, cudaFuncAttributeMaxDynamicSharedMemorySize, PROJ_SMEM);
    cudaFuncSetAttribute(kern_sim, cudaFuncAttributeMaxDynamicSharedMemorySize, SIM_SMEM);

    kern_wt<<<HH / 128, 256>>>(W);                                     // 0
    kern_proj<<<NROWS / 128, 256, PROJ_SMEM>>>(hid, bias, amask, labels); // 1
    kern_sim<<<BB * 36, 512, SIM_SMEM>>>(amask, labels, out);          // 2
}

// round 16
// speedup vs baseline: 1.2304x; 1.2304x over previous
#include <cuda_runtime.h>
#include <cuda_fp16.h>

#define BB 32
#define LL 1024
#define HH 1280
#define PP 128
#define NROWS (BB * LL)
#define INVT 14.285714285714286f
#define C1F (14.285714285714286f * 1.4426950408889634f)

// ---------------------------------------------------------------------------
// Helpers
// ---------------------------------------------------------------------------
__device__ __forceinline__ unsigned smem_to_u32(const void* p) {
    unsigned a;
    asm("{ .reg .u64 t; cvta.to.shared.u64 t, %1; cvt.u32.u64 %0, t; }" : "=r"(a) : "l"(p));
    return a;
}
static __device__ __forceinline__ unsigned sw128(unsigned off) {
    return off ^ ((off >> 3) & 0x70);
}
__device__ __forceinline__ float ex2f(float x) {
    float r;
    asm("ex2.approx.f32 %0, %1;" : "=f"(r) : "f"(x));
    return r;
}
__device__ __forceinline__ unsigned f16pack(float lo, float hi) {
    unsigned r;
    asm("cvt.rn.f16x2.f32 %0, %1, %2;" : "=r"(r) : "f"(hi), "f"(lo));
    return r;
}

#define LDSM4(r0, r1, r2, r3, addr)                                          \
    asm volatile("ldmatrix.sync.aligned.m8n8.x4.shared.b16 {%0,%1,%2,%3}, [%4];" \
                 : "=r"(r0), "=r"(r1), "=r"(r2), "=r"(r3) : "r"(addr))

#define MMA(d, a, b)                                                         \
    asm volatile("mma.sync.aligned.m16n8k16.row.col.f32.f16.f16.f32 "        \
                 "{%0,%1,%2,%3},{%4,%5,%6,%7},{%8,%9},{%0,%1,%2,%3};"        \
                 : "+f"((d)[0]), "+f"((d)[1]), "+f"((d)[2]), "+f"((d)[3])    \
                 : "r"((a)[0]), "r"((a)[1]), "r"((a)[2]), "r"((a)[3]),       \
                   "r"((b)[0]), "r"((b)[1]))

#define CP16(dst, src) \
    asm volatile("cp.async.cg.shared.global [%0], [%1], 16;" :: "r"(dst), "l"(src))
#define CP_COMMIT() asm volatile("cp.async.commit_group;" ::: "memory")
#define CP_WAIT0()  asm volatile("cp.async.wait_group 0;" ::: "memory")

// ---------------------------------------------------------------------------
// Device scratch
// ---------------------------------------------------------------------------
__device__ __align__(16) __half g_emb[NROWS * PP];
__device__ __align__(16) __half g_wt[PP * HH];   // [n][k] K-major
__device__ __align__(16) float g_se[NROWS];
__device__ __align__(16) float g_sp[NROWS];
__device__ int g_cnt4[BB * 4];
__device__ int g_cm[BB];
__device__ int g_cv[BB];
__device__ float g_partial[BB * 8];
__device__ int g_done = 0;

// ---------------------------------------------------------------------------
// Kernel 0: blocks 0..39: W -> fp16 [n][k] (32 k-rows per block).
//           blocks 40..167: zero g_se/g_sp (+ counters in block 40).
// Grid 168 >= 148 (avoids low-grid issue throttle).
// ---------------------------------------------------------------------------
__global__ __launch_bounds__(256) void kern_wt(const float* __restrict__ W) {
    const int tid = threadIdx.x;
    if (blockIdx.x >= 40) {
        const int zb = blockIdx.x - 40;            // 0..127
        int base = zb * 512 + tid * 2;             // [0, 65536)
        float2 z = make_float2(0.f, 0.f);
        if (base < NROWS) *(float2*)(g_se + base) = z;
        else              *(float2*)(g_sp + base - NROWS) = z;
        if (zb == 0) {
            if (tid < 128) g_cnt4[tid] = 0;
            else if (tid < 160) g_cm[tid - 128] = 0;
            else if (tid < 192) g_cv[tid - 160] = 0;
        }
        return;
    }
    __shared__ unsigned short smT[32 * 136];       // [k][n], pad 8
    const int k0 = blockIdx.x * 32;
#pragma unroll
    for (int i = 0; i < 4; i++) {
        int u = i * 256 + tid;                     // 0..1023
        int row = u >> 5, c4 = u & 31;             // k-row, n/4
        float4 v = *(const float4*)(W + (size_t)(k0 + row) * PP + c4 * 4);
        *(unsigned*)&smT[row * 136 + c4 * 4] = f16pack(v.x, v.y);
        *(unsigned*)&smT[row * 136 + c4 * 4 + 2] = f16pack(v.z, v.w);
    }
    __syncthreads();
#pragma unroll
    for (int i = 0; i < 2; i++) {
        int u = i * 256 + tid;                     // 0..511
        int nn = u >> 2;                           // n 0..127
        int kg = u & 3;                            // k-group 0..3
        unsigned short h[8];
#pragma unroll
        for (int j = 0; j < 8; j++) h[j] = smT[(kg * 8 + j) * 136 + nn];
        uint4 o;
        o.x = (unsigned)h[0] | ((unsigned)h[1] << 16);
        o.y = (unsigned)h[2] | ((unsigned)h[3] << 16);
        o.z = (unsigned)h[4] | ((unsigned)h[5] << 16);
        o.w = (unsigned)h[6] | ((unsigned)h[7] << 16);
        *(uint4*)(g_wt + (size_t)nn * HH + k0 + kg * 8) = o;
    }
}

// ---------------------------------------------------------------------------
// Kernel 1: proj + L2-normalize; invalid rows ZERO (R14 core, unchanged)
// ---------------------------------------------------------------------------
#define P_A(b) (2048 + (b) * 16384)
#define P_B(b) (34816 + (b) * 16384)
#define PROJ_SMEM 67584

__global__ __launch_bounds__(256, 2)
void kern_proj(const float* __restrict__ hid, const float* __restrict__ bias,
               const int* __restrict__ amask, const int* __restrict__ labels) {
    extern __shared__ char sm[];
    const unsigned sb = smem_to_u32(sm);
    const int tid = threadIdx.x, lane = tid & 31, wid = tid >> 5;
    const int wm = wid & 3, wn = wid >> 2;
    const int m0 = wm * 32, n0 = wn * 64;
    const int row0 = blockIdx.x * 128;
    float* bias_s = (float*)sm;
    float* ssbuf = (float*)(sm + 512);

    if (tid < 128) bias_s[tid] = bias[tid];

    unsigned swxA[2], swxB[4];
#pragma unroll
    for (int mt = 0; mt < 2; mt++) {
        unsigned r = m0 + mt * 16 + (lane & 15);
        swxA[mt] = sw128(r * 128 + ((lane >> 4) << 4));
    }
    {
        unsigned q = lane >> 3;
#pragma unroll
        for (int p = 0; p < 4; p++) {
            unsigned nr = n0 + p * 16 + ((q >> 1) << 3) + (lane & 7);
            swxB[p] = sw128(nr * 128 + ((q & 1) << 4));
        }
    }

    float acc[2][8][4];
#pragma unroll
    for (int mt = 0; mt < 2; mt++)
#pragma unroll
        for (int nt = 0; nt < 8; nt++)
#pragma unroll
            for (int e = 0; e < 4; e++) acc[mt][nt][e] = 0.f;

#pragma unroll
    for (int i = 0; i < 4; i++) {
        int u = i * 256 + tid;
        int n = u >> 3, k8 = u & 7;
        CP16(sb + P_B(0) + sw128((unsigned)(n * 128 + k8 * 16)),
             g_wt + (size_t)n * HH + k8 * 8);
    }
    CP_COMMIT();
#pragma unroll
    for (int q = 0; q < 4; q++) {
        int u = q * 256 + tid;
        int row = u >> 3, k8 = u & 7;
        const float* s = hid + (size_t)(row0 + row) * HH + k8 * 8;
        float4 v0 = *(const float4*)s;
        float4 v1 = *(const float4*)(s + 4);
        uint4 ra = make_uint4(f16pack(v0.x, v0.y), f16pack(v0.z, v0.w),
                              f16pack(v1.x, v1.y), f16pack(v1.z, v1.w));
        *(uint4*)(sm + P_A(0) + sw128((unsigned)(row * 128 + k8 * 16))) = ra;
    }
    CP_WAIT0();
    __syncthreads();

#pragma unroll 1
    for (int c = 0; c < 20; c++) {
        const int buf = c & 1;
        float4 va[8];
        if (c < 19) {
            const int k0n = (c + 1) * 64;
#pragma unroll
            for (int q = 0; q < 4; q++) {
                int u = q * 256 + tid;
                int row = u >> 3, k8 = u & 7;
                const float* s = hid + (size_t)(row0 + row) * HH + k0n + k8 * 8;
                va[2 * q] = *(const float4*)s;
                va[2 * q + 1] = *(const float4*)(s + 4);
            }
#pragma unroll
            for (int i = 0; i < 4; i++) {
                int u = i * 256 + tid;
                int n = u >> 3, k8 = u & 7;
                CP16(sb + P_B(buf ^ 1) + sw128((unsigned)(n * 128 + k8 * 16)),
                     g_wt + (size_t)n * HH + k0n + k8 * 8);
            }
            CP_COMMIT();
        }

        const unsigned a_base = sb + P_A(buf);
        const unsigned b_base = sb + P_B(buf);
#pragma unroll
        for (int kk = 0; kk < 4; kk++) {
            const unsigned kk2 = kk * 32;
            unsigned ah[2][4], bh[8][2];
#pragma unroll
            for (int mt = 0; mt < 2; mt++)
                LDSM4(ah[mt][0], ah[mt][1], ah[mt][2], ah[mt][3],
                      a_base + (swxA[mt] ^ kk2));
#pragma unroll
            for (int p = 0; p < 4; p++) {
                unsigned t0, t1, t2, t3;
                LDSM4(t0, t1, t2, t3, b_base + (swxB[p] ^ kk2));
                bh[2 * p][0] = t0; bh[2 * p][1] = t1;
                bh[2 * p + 1][0] = t2; bh[2 * p + 1][1] = t3;
            }
#pragma unroll
            for (int mt = 0; mt < 2; mt++)
#pragma unroll
                for (int nt = 0; nt < 8; nt++)
                    MMA(acc[mt][nt], ah[mt], bh[nt]);
        }

        if (c < 19) {
#pragma unroll
            for (int q = 0; q < 4; q++) {
                int u = q * 256 + tid;
                int row = u >> 3, k8 = u & 7;
                uint4 ra = make_uint4(
                    f16pack(va[2 * q].x, va[2 * q].y),
                    f16pack(va[2 * q].z, va[2 * q].w),
                    f16pack(va[2 * q + 1].x, va[2 * q + 1].y),
                    f16pack(va[2 * q + 1].z, va[2 * q + 1].w));
                *(uint4*)(sm + P_A(buf ^ 1) + sw128((unsigned)(row * 128 + k8 * 16))) = ra;
            }
            CP_WAIT0();
        }
        __syncthreads();
    }

    float ss[4] = {0.f, 0.f, 0.f, 0.f};
#pragma unroll
    for (int mt = 0; mt < 2; mt++)
#pragma unroll
        for (int nt = 0; nt < 8; nt++)
#pragma unroll
            for (int e = 0; e < 4; e++) {
                int s = e >> 1;
                int col = n0 + nt * 8 + (lane & 3) * 2 + (e & 1);
                float v = acc[mt][nt][e] + bias_s[col];
                acc[mt][nt][e] = v;
                ss[mt * 2 + s] += v * v;
            }
#pragma unroll
    for (int r2 = 0; r2 < 4; r2++) {
        ss[r2] += __shfl_xor_sync(0xffffffffu, ss[r2], 1);
        ss[r2] += __shfl_xor_sync(0xffffffffu, ss[r2], 2);
    }
    if ((lane & 3) == 0) {
#pragma unroll
        for (int r2 = 0; r2 < 4; r2++) {
            int rowg = wm * 32 + (r2 >> 1) * 16 + (lane >> 2) + (r2 & 1) * 8;
            ssbuf[wn * 128 + rowg] = ss[r2];
        }
    }
    __syncthreads();
#pragma unroll
    for (int r2 = 0; r2 < 4; r2++) {
        int mt = r2 >> 1, s = r2 & 1;
        int rowg = wm * 32 + mt * 16 + (lane >> 2) + s * 8;
        int gr = row0 + rowg;
        int vv = (amask[gr] != 0) && (labels[gr] != -100);
        float tot = ssbuf[rowg] + ssbuf[128 + rowg];
        float inv = rsqrtf(tot);
        inv = inv * (1.5f - 0.5f * tot * inv * inv);
        if (!vv) inv = 0.f;
        __half* oh = g_emb + (size_t)gr * PP;
#pragma unroll
        for (int nt = 0; nt < 8; nt++) {
            int col = n0 + nt * 8 + (lane & 3) * 2;
            *(unsigned*)(oh + col) =
                f16pack(acc[mt][nt][s * 2] * inv, acc[mt][nt][s * 2 + 1] * inv);
        }
    }
}

// ---------------------------------------------------------------------------
// Kernel 2: SYMMETRIC sim (R14 core, unchanged). Grid 32 x 36 upper-tri.
// ---------------------------------------------------------------------------
#define SMS_LABJ   0
#define SMS_POSM   512
#define SMS_ROWRED 1024
#define SMS_COLRED 5120
#define SMS_A      10240
#define SMS_B      43008
#define SIM_SMEM   75776

__global__ __launch_bounds__(512)
void kern_sim(const int* __restrict__ amask, const int* __restrict__ labels) {
    extern __shared__ char sm[];
    const unsigned sb = smem_to_u32(sm);
    const int tid = threadIdx.x, lane = tid & 31, wid = tid >> 5;
    const int wm = wid & 3, wn = wid >> 2;
    const int m0 = wm * 32, n0 = wn * 32;
    const int b = blockIdx.x / 36;
    int p = blockIdx.x % 36;
    int it = 0;
    while (p >= 8 - it) { p -= 8 - it; it++; }
    const int jt = it + p;
    const int diag = (it == jt);
    const int i0 = it * 128, j0 = jt * 128;
    const __half* eb = g_emb + (size_t)b * LL * PP;
    int* labjp = (int*)sm;
    unsigned* posm = (unsigned*)(sm + SMS_POSM);
    float* rowred = (float*)(sm + SMS_ROWRED);
    float* colred = (float*)(sm + SMS_COLRED);

#pragma unroll
    for (int i = 0; i < 4; i++) {
        int u = i * 512 + tid;
        int row = u >> 4, k8 = u & 15;
        unsigned off = (unsigned)((k8 >> 3) * 16384) +
                       sw128((unsigned)(row * 128 + (k8 & 7) * 16));
        CP16(sb + SMS_A + off, eb + (size_t)(i0 + row) * PP + k8 * 8);
    }
    if (!diag) {
#pragma unroll
        for (int i = 0; i < 4; i++) {
            int u = i * 512 + tid;
            int row = u >> 4, k8 = u & 15;
            unsigned off = (unsigned)((k8 >> 3) * 16384) +
                           sw128((unsigned)(row * 128 + (k8 & 7) * 16));
            CP16(sb + SMS_B + off, eb + (size_t)(j0 + row) * PP + k8 * 8);
        }
    }
    CP_COMMIT();

    if (tid < 128) {
        int mm = amask[b * LL + j0 + tid];
        int lb = labels[b * LL + j0 + tid];
        int vv = (mm != 0) && (lb != -100);
        labjp[tid] = lb;
#pragma unroll
        for (int l = 0; l < 4; l++) {
            unsigned pb = __ballot_sync(0xffffffffu, vv && (lb == l));
            if (lane == 0) {
                posm[l * 4 + wid] = pb;
                if (diag) atomicAdd(&g_cnt4[b * 4 + l], __popc(pb));
            }
        }
        if (diag) {
            unsigned mb = __ballot_sync(0xffffffffu, mm != 0);
            unsigned vb = __ballot_sync(0xffffffffu, vv);
            if (lane == 0) {
                atomicAdd(&g_cm[b], __popc(mb));
                atomicAdd(&g_cv[b], __popc(vb));
            }
        }
    }

    int labi_[4];
#pragma unroll
    for (int r2 = 0; r2 < 4; r2++) {
        int rowg = m0 + (r2 >> 1) * 16 + (lane >> 2) + (r2 & 1) * 8;
        int gi = b * LL + i0 + rowg;
        int lb = labels[gi];
        labi_[r2] = ((amask[gi] != 0) && (lb != -100)) ? lb : -1;
    }

    unsigned swxA[2], swxB[2];
#pragma unroll
    for (int mt = 0; mt < 2; mt++) {
        unsigned r = m0 + mt * 16 + (lane & 15);
        swxA[mt] = sw128(r * 128 + ((lane >> 4) << 4));
    }
    {
        unsigned q = lane >> 3;
#pragma unroll
        for (int pq = 0; pq < 2; pq++) {
            unsigned nr = n0 + pq * 16 + ((q >> 1) << 3) + (lane & 7);
            swxB[pq] = sw128(nr * 128 + ((q & 1) << 4));
        }
    }

    CP_WAIT0();
    __syncthreads();

    float acc[2][4][4];
#pragma unroll
    for (int mt = 0; mt < 2; mt++)
#pragma unroll
        for (int nt = 0; nt < 4; nt++)
#pragma unroll
            for (int e = 0; e < 4; e++) acc[mt][nt][e] = 0.f;

    const unsigned aT = sb + SMS_A;
    const unsigned bT = diag ? (sb + SMS_A) : (sb + SMS_B);
#pragma unroll
    for (int kk = 0; kk < 8; kk++) {
        const unsigned ch = (unsigned)((kk >> 2) * 16384);
        const unsigned kk2 = (kk & 3) * 32;
        unsigned ah[2][4], bh[4][2];
#pragma unroll
        for (int mt = 0; mt < 2; mt++)
            LDSM4(ah[mt][0], ah[mt][1], ah[mt][2], ah[mt][3],
                  aT + ch + (swxA[mt] ^ kk2));
#pragma unroll
        for (int pq = 0; pq < 2; pq++) {
            unsigned t0, t1, t2, t3;
            LDSM4(t0, t1, t2, t3, bT + ch + (swxB[pq] ^ kk2));
            bh[2 * pq][0] = t0; bh[2 * pq][1] = t1;
            bh[2 * pq + 1][0] = t2; bh[2 * pq + 1][1] = t3;
        }
#pragma unroll
        for (int mt = 0; mt < 2; mt++)
#pragma unroll
            for (int nt = 0; nt < 4; nt++)
                MMA(acc[mt][nt], ah[mt], bh[nt]);
    }

    const int sh = (lane & 3) * 2;
    float se_[4] = {0.f, 0.f, 0.f, 0.f}, sp_[4] = {0.f, 0.f, 0.f, 0.f};
    float colse[8], colsp[8];
    int lbjv[8];
#pragma unroll
    for (int idx = 0; idx < 8; idx++) { colse[idx] = 0.f; colsp[idx] = 0.f; }
    if (!diag) {
#pragma unroll
        for (int idx = 0; idx < 8; idx++)
            lbjv[idx] = labjp[n0 + (idx >> 1) * 8 + sh + (idx & 1)];
    }

#pragma unroll
    for (int r2 = 0; r2 < 4; r2++) {
        const int mt = r2 >> 1, s = r2 & 1;
        const int rowg = m0 + mt * 16 + (lane >> 2) + s * 8;
        const int labi = labi_[r2];
        unsigned pmr = (labi >= 0) ? posm[labi * 4 + wn] : 0u;
        if (diag) {
            const int selfhere = ((rowg >> 5) == wn);
            const int bps = rowg & 31;
            if (selfhere) pmr &= ~(1u << bps);
#pragma unroll
            for (int nt = 0; nt < 4; nt++)
#pragma unroll
                for (int cc = 0; cc < 2; cc++) {
                    int bp = nt * 8 + sh + cc;
                    float a = acc[mt][nt][s * 2 + cc];
                    float e = ex2f(fmaf(a, C1F, -C1F));
                    if (selfhere && bp == bps) e = 0.f;
                    se_[r2] += e;
                    if ((pmr >> bp) & 1) sp_[r2] += a;
                }
        } else {
#pragma unroll
            for (int nt = 0; nt < 4; nt++)
#pragma unroll
                for (int cc = 0; cc < 2; cc++) {
                    int idx = nt * 2 + cc;
                    int bp = nt * 8 + sh + cc;
                    float a = acc[mt][nt][s * 2 + cc];
                    float e = ex2f(fmaf(a, C1F, -C1F));
                    se_[r2] += e;
                    colse[idx] += e;
                    if ((pmr >> bp) & 1) sp_[r2] += a;
                    colsp[idx] += (labi == lbjv[idx]) ? a : 0.f;
                }
        }
    }

#pragma unroll
    for (int o = 1; o <= 2; o <<= 1)
#pragma unroll
        for (int r2 = 0; r2 < 4; r2++) {
            se_[r2] += __shfl_xor_sync(0xffffffffu, se_[r2], o);
            sp_[r2] += __shfl_xor_sync(0xffffffffu, sp_[r2], o);
        }
    if ((lane & 3) == 0) {
#pragma unroll
        for (int r2 = 0; r2 < 4; r2++) {
            int rowg = m0 + (r2 >> 1) * 16 + (lane >> 2) + (r2 & 1) * 8;
            rowred[(wn * 128 + rowg) * 2] = se_[r2];
            rowred[(wn * 128 + rowg) * 2 + 1] = sp_[r2];
        }
    }
    if (!diag) {
#pragma unroll
        for (int idx = 0; idx < 8; idx++)
#pragma unroll
            for (int o = 4; o <= 16; o <<= 1) {
                colse[idx] += __shfl_xor_sync(0xffffffffu, colse[idx], o);
                colsp[idx] += __shfl_xor_sync(0xffffffffu, colsp[idx], o);
            }
        if ((lane >> 2) == 0) {
#pragma unroll
            for (int idx = 0; idx < 8; idx++) {
                int col = n0 + (idx >> 1) * 8 + sh + (idx & 1);
                colred[(wm * 128 + col) * 2] = colse[idx];
                colred[(wm * 128 + col) * 2 + 1] = colsp[idx];
            }
        }
    }
    __syncthreads();

    if (tid < 256) {
        int row = tid >> 1, st = tid & 1;
        float v = rowred[row * 2 + st] + rowred[(128 + row) * 2 + st] +
                  rowred[(256 + row) * 2 + st] + rowred[(384 + row) * 2 + st];
        atomicAdd((st ? g_sp : g_se) + b * LL + i0 + row, v);
    } else if (!diag) {
        int u = tid - 256;
        int col = u >> 1, st = u & 1;
        float v = colred[col * 2 + st] + colred[(128 + col) * 2 + st] +
                  colred[(256 + col) * 2 + st] + colred[(384 + col) * 2 + st];
        atomicAdd((st ? g_sp : g_se) + b * LL + j0 + col, v);
    }
}

// ---------------------------------------------------------------------------
// Kernel 3: per-anchor loss + deterministic final scalar (last CTA).
// Grid 256 CTAs (>=148, avoids low-grid throttle) x 128 threads.
// ---------------------------------------------------------------------------
__global__ __launch_bounds__(128)
void kern_loss(const int* __restrict__ amask, const int* __restrict__ labels,
               float* __restrict__ out) {
    __shared__ float wp[4];
    __shared__ int lastf;
    const int tid = threadIdx.x, lane = tid & 31, wid = tid >> 5;
    const int b = blockIdx.x >> 3;
    const int a = b * LL + (blockIdx.x & 7) * 128 + tid;

    int lb = labels[a];
    int valid = (amask[a] != 0) && (lb != -100);
    float al = 0.f;
    if (valid) {
        int cv = g_cv[b];
        float sec = g_se[a] - (float)(LL - cv) * ex2f(-C1F);
        sec = fmaxf(sec, 0.f) + 1e-12f;
        float npf = (float)(g_cnt4[b * 4 + lb] - 1);
        al = (INVT * g_sp[a] - npf * (INVT + __logf(sec))) / (npf + 1e-12f);
    }
#pragma unroll
    for (int o = 16; o >= 1; o >>= 1) al += __shfl_xor_sync(0xffffffffu, al, o);
    if (lane == 0) wp[wid] = al;
    __syncthreads();
    if (tid == 0)
        g_partial[blockIdx.x] = wp[0] + wp[1] + wp[2] + wp[3];
    __threadfence();
    if (tid == 0) lastf = (atomicAdd(&g_done, 1) == 255);
    __syncthreads();
    if (lastf) {
        __threadfence();
        if (tid < 32) {
            float ps = 0.f;
#pragma unroll
            for (int k = 0; k < 8; k++) ps += __ldcg(&g_partial[tid * 8 + k]);
            int cm = __ldcg(&g_cm[tid]);
            int cv = __ldcg(&g_cv[tid]);
            int ok = (cm >= 2);
            float nvv = (float)(cv >= 1 ? cv : 1);
            float lossb = ok ? (-ps / nvv) : 0.f;
            int ns = ok;
#pragma unroll
            for (int o = 16; o >= 1; o >>= 1) {
                lossb += __shfl_xor_sync(0xffffffffu, lossb, o);
                ns += __shfl_xor_sync(0xffffffffu, ns, o);
            }
            if (tid == 0) {
                out[0] = lossb / (float)(ns > 0 ? ns : 1);
                g_done = 0;
            }
        }
    }
}

// ---------------------------------------------------------------------------
extern "C" void kernel_launch(void* const* d_in, const int* in_sizes, int n_in,
                              void* d_out, int out_size) {
    const float* hid = (const float*)d_in[0];
    const float* W = (const float*)d_in[1];
    const float* bias = (const float*)d_in[2];
    const int* amask = (const int*)d_in[3];
    const int* labels = (const int*)d_in[4];
    float* out = (float*)d_out;

    cudaFuncSetAttribute(kern_proj, cudaFuncAttributeMaxDynamicSharedMemorySize, PROJ_SMEM);
    cudaFuncSetAttribute(kern_sim, cudaFuncAttributeMaxDynamicSharedMemorySize, SIM_SMEM);

    kern_wt<<<168, 256>>>(W);                                          // 0
    kern_proj<<<NROWS / 128, 256, PROJ_SMEM>>>(hid, bias, amask, labels); // 1
    kern_sim<<<BB * 36, 512, SIM_SMEM>>>(amask, labels);               // 2
    kern_loss<<<256, 128>>>(amask, labels, out);                       // 3
}

// round 17
// speedup vs baseline: 1.3277x; 1.0791x over previous
#include <cuda_runtime.h>
#include <cuda_fp16.h>

#define BB 32
#define LL 1024
#define HH 1280
#define PP 128
#define NROWS (BB * LL)
#define INVT 14.285714285714286f
#define C1F (14.285714285714286f * 1.4426950408889634f)

// ---------------------------------------------------------------------------
// Helpers
// ---------------------------------------------------------------------------
__device__ __forceinline__ unsigned smem_to_u32(const void* p) {
    unsigned a;
    asm("{ .reg .u64 t; cvta.to.shared.u64 t, %1; cvt.u32.u64 %0, t; }" : "=r"(a) : "l"(p));
    return a;
}
static __device__ __forceinline__ unsigned sw128(unsigned off) {
    return off ^ ((off >> 3) & 0x70);
}
__device__ __forceinline__ float ex2f(float x) {
    float r;
    asm("ex2.approx.f32 %0, %1;" : "=f"(r) : "f"(x));
    return r;
}
__device__ __forceinline__ unsigned f16pack(float lo, float hi) {
    unsigned r;
    asm("cvt.rn.f16x2.f32 %0, %1, %2;" : "=r"(r) : "f"(hi), "f"(lo));
    return r;
}

#define LDSM4(r0, r1, r2, r3, addr)                                          \
    asm volatile("ldmatrix.sync.aligned.m8n8.x4.shared.b16 {%0,%1,%2,%3}, [%4];" \
                 : "=r"(r0), "=r"(r1), "=r"(r2), "=r"(r3) : "r"(addr))

#define MMA(d, a, b)                                                         \
    asm volatile("mma.sync.aligned.m16n8k16.row.col.f32.f16.f16.f32 "        \
                 "{%0,%1,%2,%3},{%4,%5,%6,%7},{%8,%9},{%0,%1,%2,%3};"        \
                 : "+f"((d)[0]), "+f"((d)[1]), "+f"((d)[2]), "+f"((d)[3])    \
                 : "r"((a)[0]), "r"((a)[1]), "r"((a)[2]), "r"((a)[3]),       \
                   "r"((b)[0]), "r"((b)[1]))

#define CP16(dst, src) \
    asm volatile("cp.async.cg.shared.global [%0], [%1], 16;" :: "r"(dst), "l"(src))
#define CP_COMMIT() asm volatile("cp.async.commit_group;" ::: "memory")
#define CP_WAIT0()  asm volatile("cp.async.wait_group 0;" ::: "memory")

// ---------------------------------------------------------------------------
// Device scratch
// ---------------------------------------------------------------------------
__device__ __align__(16) __half g_emb[NROWS * PP];
__device__ __align__(16) __half g_wt[PP * HH];   // [n][k] K-major
__device__ __align__(16) float g_se[NROWS];
__device__ __align__(16) float g_sp[NROWS];
__device__ int g_cnt4[BB * 4];
__device__ int g_cm[BB];
__device__ int g_cv[BB];
__device__ float g_partial[BB * 8];
__device__ int g_done = 0;

// ---------------------------------------------------------------------------
// Kernel 0: blocks 0..39: W -> fp16 [n][k] (32 k-rows per block).
//           blocks 40..167: zero g_se/g_sp (+ counters in block 40).
// ---------------------------------------------------------------------------
__global__ __launch_bounds__(256) void kern_wt(const float* __restrict__ W) {
    const int tid = threadIdx.x;
    if (blockIdx.x >= 40) {
        const int zb = blockIdx.x - 40;
        int base = zb * 512 + tid * 2;
        float2 z = make_float2(0.f, 0.f);
        if (base < NROWS) *(float2*)(g_se + base) = z;
        else              *(float2*)(g_sp + base - NROWS) = z;
        if (zb == 0) {
            if (tid < 128) g_cnt4[tid] = 0;
            else if (tid < 160) g_cm[tid - 128] = 0;
            else if (tid < 192) g_cv[tid - 160] = 0;
        }
        return;
    }
    __shared__ unsigned short smT[32 * 136];
    const int k0 = blockIdx.x * 32;
#pragma unroll
    for (int i = 0; i < 4; i++) {
        int u = i * 256 + tid;
        int row = u >> 5, c4 = u & 31;
        float4 v = *(const float4*)(W + (size_t)(k0 + row) * PP + c4 * 4);
        *(unsigned*)&smT[row * 136 + c4 * 4] = f16pack(v.x, v.y);
        *(unsigned*)&smT[row * 136 + c4 * 4 + 2] = f16pack(v.z, v.w);
    }
    __syncthreads();
#pragma unroll
    for (int i = 0; i < 2; i++) {
        int u = i * 256 + tid;
        int nn = u >> 2;
        int kg = u & 3;
        unsigned short h[8];
#pragma unroll
        for (int j = 0; j < 8; j++) h[j] = smT[(kg * 8 + j) * 136 + nn];
        uint4 o;
        o.x = (unsigned)h[0] | ((unsigned)h[1] << 16);
        o.y = (unsigned)h[2] | ((unsigned)h[3] << 16);
        o.z = (unsigned)h[4] | ((unsigned)h[5] << 16);
        o.w = (unsigned)h[6] | ((unsigned)h[7] << 16);
        *(uint4*)(g_wt + (size_t)nn * HH + k0 + kg * 8) = o;
    }
}

// ---------------------------------------------------------------------------
// Kernel 1: proj + L2-normalize; invalid rows ZERO (unchanged)
// ---------------------------------------------------------------------------
#define P_A(b) (2048 + (b) * 16384)
#define P_B(b) (34816 + (b) * 16384)
#define PROJ_SMEM 67584

__global__ __launch_bounds__(256, 2)
void kern_proj(const float* __restrict__ hid, const float* __restrict__ bias,
               const int* __restrict__ amask, const int* __restrict__ labels) {
    extern __shared__ char sm[];
    const unsigned sb = smem_to_u32(sm);
    const int tid = threadIdx.x, lane = tid & 31, wid = tid >> 5;
    const int wm = wid & 3, wn = wid >> 2;
    const int m0 = wm * 32, n0 = wn * 64;
    const int row0 = blockIdx.x * 128;
    float* bias_s = (float*)sm;
    float* ssbuf = (float*)(sm + 512);

    if (tid < 128) bias_s[tid] = bias[tid];

    unsigned swxA[2], swxB[4];
#pragma unroll
    for (int mt = 0; mt < 2; mt++) {
        unsigned r = m0 + mt * 16 + (lane & 15);
        swxA[mt] = sw128(r * 128 + ((lane >> 4) << 4));
    }
    {
        unsigned q = lane >> 3;
#pragma unroll
        for (int p = 0; p < 4; p++) {
            unsigned nr = n0 + p * 16 + ((q >> 1) << 3) + (lane & 7);
            swxB[p] = sw128(nr * 128 + ((q & 1) << 4));
        }
    }

    float acc[2][8][4];
#pragma unroll
    for (int mt = 0; mt < 2; mt++)
#pragma unroll
        for (int nt = 0; nt < 8; nt++)
#pragma unroll
            for (int e = 0; e < 4; e++) acc[mt][nt][e] = 0.f;

#pragma unroll
    for (int i = 0; i < 4; i++) {
        int u = i * 256 + tid;
        int n = u >> 3, k8 = u & 7;
        CP16(sb + P_B(0) + sw128((unsigned)(n * 128 + k8 * 16)),
             g_wt + (size_t)n * HH + k8 * 8);
    }
    CP_COMMIT();
#pragma unroll
    for (int q = 0; q < 4; q++) {
        int u = q * 256 + tid;
        int row = u >> 3, k8 = u & 7;
        const float* s = hid + (size_t)(row0 + row) * HH + k8 * 8;
        float4 v0 = *(const float4*)s;
        float4 v1 = *(const float4*)(s + 4);
        uint4 ra = make_uint4(f16pack(v0.x, v0.y), f16pack(v0.z, v0.w),
                              f16pack(v1.x, v1.y), f16pack(v1.z, v1.w));
        *(uint4*)(sm + P_A(0) + sw128((unsigned)(row * 128 + k8 * 16))) = ra;
    }
    CP_WAIT0();
    __syncthreads();

#pragma unroll 1
    for (int c = 0; c < 20; c++) {
        const int buf = c & 1;
        float4 va[8];
        if (c < 19) {
            const int k0n = (c + 1) * 64;
#pragma unroll
            for (int q = 0; q < 4; q++) {
                int u = q * 256 + tid;
                int row = u >> 3, k8 = u & 7;
                const float* s = hid + (size_t)(row0 + row) * HH + k0n + k8 * 8;
                va[2 * q] = *(const float4*)s;
                va[2 * q + 1] = *(const float4*)(s + 4);
            }
#pragma unroll
            for (int i = 0; i < 4; i++) {
                int u = i * 256 + tid;
                int n = u >> 3, k8 = u & 7;
                CP16(sb + P_B(buf ^ 1) + sw128((unsigned)(n * 128 + k8 * 16)),
                     g_wt + (size_t)n * HH + k0n + k8 * 8);
            }
            CP_COMMIT();
        }

        const unsigned a_base = sb + P_A(buf);
        const unsigned b_base = sb + P_B(buf);
#pragma unroll
        for (int kk = 0; kk < 4; kk++) {
            const unsigned kk2 = kk * 32;
            unsigned ah[2][4], bh[8][2];
#pragma unroll
            for (int mt = 0; mt < 2; mt++)
                LDSM4(ah[mt][0], ah[mt][1], ah[mt][2], ah[mt][3],
                      a_base + (swxA[mt] ^ kk2));
#pragma unroll
            for (int p = 0; p < 4; p++) {
                unsigned t0, t1, t2, t3;
                LDSM4(t0, t1, t2, t3, b_base + (swxB[p] ^ kk2));
                bh[2 * p][0] = t0; bh[2 * p][1] = t1;
                bh[2 * p + 1][0] = t2; bh[2 * p + 1][1] = t3;
            }
#pragma unroll
            for (int mt = 0; mt < 2; mt++)
#pragma unroll
                for (int nt = 0; nt < 8; nt++)
                    MMA(acc[mt][nt], ah[mt], bh[nt]);
        }

        if (c < 19) {
#pragma unroll
            for (int q = 0; q < 4; q++) {
                int u = q * 256 + tid;
                int row = u >> 3, k8 = u & 7;
                uint4 ra = make_uint4(
                    f16pack(va[2 * q].x, va[2 * q].y),
                    f16pack(va[2 * q].z, va[2 * q].w),
                    f16pack(va[2 * q + 1].x, va[2 * q + 1].y),
                    f16pack(va[2 * q + 1].z, va[2 * q + 1].w));
                *(uint4*)(sm + P_A(buf ^ 1) + sw128((unsigned)(row * 128 + k8 * 16))) = ra;
            }
            CP_WAIT0();
        }
        __syncthreads();
    }

    float ss[4] = {0.f, 0.f, 0.f, 0.f};
#pragma unroll
    for (int mt = 0; mt < 2; mt++)
#pragma unroll
        for (int nt = 0; nt < 8; nt++)
#pragma unroll
            for (int e = 0; e < 4; e++) {
                int s = e >> 1;
                int col = n0 + nt * 8 + (lane & 3) * 2 + (e & 1);
                float v = acc[mt][nt][e] + bias_s[col];
                acc[mt][nt][e] = v;
                ss[mt * 2 + s] += v * v;
            }
#pragma unroll
    for (int r2 = 0; r2 < 4; r2++) {
        ss[r2] += __shfl_xor_sync(0xffffffffu, ss[r2], 1);
        ss[r2] += __shfl_xor_sync(0xffffffffu, ss[r2], 2);
    }
    if ((lane & 3) == 0) {
#pragma unroll
        for (int r2 = 0; r2 < 4; r2++) {
            int rowg = wm * 32 + (r2 >> 1) * 16 + (lane >> 2) + (r2 & 1) * 8;
            ssbuf[wn * 128 + rowg] = ss[r2];
        }
    }
    __syncthreads();
#pragma unroll
    for (int r2 = 0; r2 < 4; r2++) {
        int mt = r2 >> 1, s = r2 & 1;
        int rowg = wm * 32 + mt * 16 + (lane >> 2) + s * 8;
        int gr = row0 + rowg;
        int vv = (amask[gr] != 0) && (labels[gr] != -100);
        float tot = ssbuf[rowg] + ssbuf[128 + rowg];
        float inv = rsqrtf(tot);
        inv = inv * (1.5f - 0.5f * tot * inv * inv);
        if (!vv) inv = 0.f;
        __half* oh = g_emb + (size_t)gr * PP;
#pragma unroll
        for (int nt = 0; nt < 8; nt++) {
            int col = n0 + nt * 8 + (lane & 3) * 2;
            *(unsigned*)(oh + col) =
                f16pack(acc[mt][nt][s * 2] * inv, acc[mt][nt][s * 2 + 1] * inv);
        }
    }
}

// ---------------------------------------------------------------------------
// Kernel 2: SYMMETRIC sim, OCCUPANCY 2 (64-reg cap). colsp shares the pmr
// gate (identical predicate); lbjv/labjp removed (fewer regs + loads).
// ---------------------------------------------------------------------------
#define SMS_POSM   512
#define SMS_ROWRED 1024
#define SMS_COLRED 5120
#define SMS_A      10240
#define SMS_B      43008
#define SIM_SMEM   75776

__global__ __launch_bounds__(512, 2)
void kern_sim(const int* __restrict__ amask, const int* __restrict__ labels) {
    extern __shared__ char sm[];
    const unsigned sb = smem_to_u32(sm);
    const int tid = threadIdx.x, lane = tid & 31, wid = tid >> 5;
    const int wm = wid & 3, wn = wid >> 2;
    const int m0 = wm * 32, n0 = wn * 32;
    const int b = blockIdx.x / 36;
    int p = blockIdx.x % 36;
    int it = 0;
    while (p >= 8 - it) { p -= 8 - it; it++; }
    const int jt = it + p;
    const int diag = (it == jt);
    const int i0 = it * 128, j0 = jt * 128;
    const __half* eb = g_emb + (size_t)b * LL * PP;
    unsigned* posm = (unsigned*)(sm + SMS_POSM);
    float* rowred = (float*)(sm + SMS_ROWRED);
    float* colred = (float*)(sm + SMS_COLRED);

#pragma unroll
    for (int i = 0; i < 4; i++) {
        int u = i * 512 + tid;
        int row = u >> 4, k8 = u & 15;
        unsigned off = (unsigned)((k8 >> 3) * 16384) +
                       sw128((unsigned)(row * 128 + (k8 & 7) * 16));
        CP16(sb + SMS_A + off, eb + (size_t)(i0 + row) * PP + k8 * 8);
    }
    if (!diag) {
#pragma unroll
        for (int i = 0; i < 4; i++) {
            int u = i * 512 + tid;
            int row = u >> 4, k8 = u & 15;
            unsigned off = (unsigned)((k8 >> 3) * 16384) +
                           sw128((unsigned)(row * 128 + (k8 & 7) * 16));
            CP16(sb + SMS_B + off, eb + (size_t)(j0 + row) * PP + k8 * 8);
        }
    }
    CP_COMMIT();

    if (tid < 128) {
        int mm = amask[b * LL + j0 + tid];
        int lb = labels[b * LL + j0 + tid];
        int vv = (mm != 0) && (lb != -100);
#pragma unroll
        for (int l = 0; l < 4; l++) {
            unsigned pb = __ballot_sync(0xffffffffu, vv && (lb == l));
            if (lane == 0) {
                posm[l * 4 + wid] = pb;
                if (diag) atomicAdd(&g_cnt4[b * 4 + l], __popc(pb));
            }
        }
        if (diag) {
            unsigned mb = __ballot_sync(0xffffffffu, mm != 0);
            unsigned vb = __ballot_sync(0xffffffffu, vv);
            if (lane == 0) {
                atomicAdd(&g_cm[b], __popc(mb));
                atomicAdd(&g_cv[b], __popc(vb));
            }
        }
    }

    int labi_[4];
#pragma unroll
    for (int r2 = 0; r2 < 4; r2++) {
        int rowg = m0 + (r2 >> 1) * 16 + (lane >> 2) + (r2 & 1) * 8;
        int gi = b * LL + i0 + rowg;
        int lb = labels[gi];
        labi_[r2] = ((amask[gi] != 0) && (lb != -100)) ? lb : -1;
    }

    unsigned swxA[2], swxB[2];
#pragma unroll
    for (int mt = 0; mt < 2; mt++) {
        unsigned r = m0 + mt * 16 + (lane & 15);
        swxA[mt] = sw128(r * 128 + ((lane >> 4) << 4));
    }
    {
        unsigned q = lane >> 3;
#pragma unroll
        for (int pq = 0; pq < 2; pq++) {
            unsigned nr = n0 + pq * 16 + ((q >> 1) << 3) + (lane & 7);
            swxB[pq] = sw128(nr * 128 + ((q & 1) << 4));
        }
    }

    CP_WAIT0();
    __syncthreads();

    float acc[2][4][4];
#pragma unroll
    for (int mt = 0; mt < 2; mt++)
#pragma unroll
        for (int nt = 0; nt < 4; nt++)
#pragma unroll
            for (int e = 0; e < 4; e++) acc[mt][nt][e] = 0.f;

    const unsigned aT = sb + SMS_A;
    const unsigned bT = diag ? (sb + SMS_A) : (sb + SMS_B);
#pragma unroll
    for (int kk = 0; kk < 8; kk++) {
        const unsigned ch = (unsigned)((kk >> 2) * 16384);
        const unsigned kk2 = (kk & 3) * 32;
        unsigned ah[2][4], bh[4][2];
#pragma unroll
        for (int mt = 0; mt < 2; mt++)
            LDSM4(ah[mt][0], ah[mt][1], ah[mt][2], ah[mt][3],
                  aT + ch + (swxA[mt] ^ kk2));
#pragma unroll
        for (int pq = 0; pq < 2; pq++) {
            unsigned t0, t1, t2, t3;
            LDSM4(t0, t1, t2, t3, bT + ch + (swxB[pq] ^ kk2));
            bh[2 * pq][0] = t0; bh[2 * pq][1] = t1;
            bh[2 * pq + 1][0] = t2; bh[2 * pq + 1][1] = t3;
        }
#pragma unroll
        for (int mt = 0; mt < 2; mt++)
#pragma unroll
            for (int nt = 0; nt < 4; nt++)
                MMA(acc[mt][nt], ah[mt], bh[nt]);
    }

    const int sh = (lane & 3) * 2;
    float se_[4] = {0.f, 0.f, 0.f, 0.f}, sp_[4] = {0.f, 0.f, 0.f, 0.f};
    float colse[8], colsp[8];
#pragma unroll
    for (int idx = 0; idx < 8; idx++) { colse[idx] = 0.f; colsp[idx] = 0.f; }

#pragma unroll
    for (int r2 = 0; r2 < 4; r2++) {
        const int mt = r2 >> 1, s = r2 & 1;
        const int rowg = m0 + mt * 16 + (lane >> 2) + s * 8;
        const int labi = labi_[r2];
        unsigned pmr = (labi >= 0) ? posm[labi * 4 + wn] : 0u;
        if (diag) {
            const int selfhere = ((rowg >> 5) == wn);
            const int bps = rowg & 31;
            if (selfhere) pmr &= ~(1u << bps);
#pragma unroll
            for (int nt = 0; nt < 4; nt++)
#pragma unroll
                for (int cc = 0; cc < 2; cc++) {
                    int bp = nt * 8 + sh + cc;
                    float a = acc[mt][nt][s * 2 + cc];
                    float e = ex2f(fmaf(a, C1F, -C1F));
                    if (selfhere && bp == bps) e = 0.f;
                    se_[r2] += e;
                    if ((pmr >> bp) & 1) sp_[r2] += a;
                }
        } else {
#pragma unroll
            for (int nt = 0; nt < 4; nt++)
#pragma unroll
                for (int cc = 0; cc < 2; cc++) {
                    int idx = nt * 2 + cc;
                    int bp = nt * 8 + sh + cc;
                    float a = acc[mt][nt][s * 2 + cc];
                    float e = ex2f(fmaf(a, C1F, -C1F));
                    se_[r2] += e;
                    colse[idx] += e;
                    if ((pmr >> bp) & 1) { sp_[r2] += a; colsp[idx] += a; }
                }
        }
    }

#pragma unroll
    for (int o = 1; o <= 2; o <<= 1)
#pragma unroll
        for (int r2 = 0; r2 < 4; r2++) {
            se_[r2] += __shfl_xor_sync(0xffffffffu, se_[r2], o);
            sp_[r2] += __shfl_xor_sync(0xffffffffu, sp_[r2], o);
        }
    if ((lane & 3) == 0) {
#pragma unroll
        for (int r2 = 0; r2 < 4; r2++) {
            int rowg = m0 + (r2 >> 1) * 16 + (lane >> 2) + (r2 & 1) * 8;
            rowred[(wn * 128 + rowg) * 2] = se_[r2];
            rowred[(wn * 128 + rowg) * 2 + 1] = sp_[r2];
        }
    }
    if (!diag) {
#pragma unroll
        for (int idx = 0; idx < 8; idx++)
#pragma unroll
            for (int o = 4; o <= 16; o <<= 1) {
                colse[idx] += __shfl_xor_sync(0xffffffffu, colse[idx], o);
                colsp[idx] += __shfl_xor_sync(0xffffffffu, colsp[idx], o);
            }
        if ((lane >> 2) == 0) {
#pragma unroll
            for (int idx = 0; idx < 8; idx++) {
                int col = n0 + (idx >> 1) * 8 + sh + (idx & 1);
                colred[(wm * 128 + col) * 2] = colse[idx];
                colred[(wm * 128 + col) * 2 + 1] = colsp[idx];
            }
        }
    }
    __syncthreads();

    if (tid < 256) {
        int row = tid >> 1, st = tid & 1;
        float v = rowred[row * 2 + st] + rowred[(128 + row) * 2 + st] +
                  rowred[(256 + row) * 2 + st] + rowred[(384 + row) * 2 + st];
        atomicAdd((st ? g_sp : g_se) + b * LL + i0 + row, v);
    } else if (!diag) {
        int u = tid - 256;
        int col = u >> 1, st = u & 1;
        float v = colred[col * 2 + st] + colred[(128 + col) * 2 + st] +
                  colred[(256 + col) * 2 + st] + colred[(384 + col) * 2 + st];
        atomicAdd((st ? g_sp : g_se) + b * LL + j0 + col, v);
    }
}

// ---------------------------------------------------------------------------
// Kernel 3: per-anchor loss + deterministic final scalar (last CTA).
// ---------------------------------------------------------------------------
__global__ __launch_bounds__(128)
void kern_loss(const int* __restrict__ amask, const int* __restrict__ labels,
               float* __restrict__ out) {
    __shared__ float wp[4];
    __shared__ int lastf;
    const int tid = threadIdx.x, lane = tid & 31, wid = tid >> 5;
    const int b = blockIdx.x >> 3;
    const int a = b * LL + (blockIdx.x & 7) * 128 + tid;

    int lb = labels[a];
    int valid = (amask[a] != 0) && (lb != -100);
    float al = 0.f;
    if (valid) {
        int cv = g_cv[b];
        float sec = g_se[a] - (float)(LL - cv) * ex2f(-C1F);
        sec = fmaxf(sec, 0.f) + 1e-12f;
        float npf = (float)(g_cnt4[b * 4 + lb] - 1);
        al = (INVT * g_sp[a] - npf * (INVT + __logf(sec))) / (npf + 1e-12f);
    }
#pragma unroll
    for (int o = 16; o >= 1; o >>= 1) al += __shfl_xor_sync(0xffffffffu, al, o);
    if (lane == 0) wp[wid] = al;
    __syncthreads();
    if (tid == 0)
        g_partial[blockIdx.x] = wp[0] + wp[1] + wp[2] + wp[3];
    __threadfence();
    if (tid == 0) lastf = (atomicAdd(&g_done, 1) == 255);
    __syncthreads();
    if (lastf) {
        __threadfence();
        if (tid < 32) {
            float ps = 0.f;
#pragma unroll
            for (int k = 0; k < 8; k++) ps += __ldcg(&g_partial[tid * 8 + k]);
            int cm = __ldcg(&g_cm[tid]);
            int cv = __ldcg(&g_cv[tid]);
            int ok = (cm >= 2);
            float nvv = (float)(cv >= 1 ? cv : 1);
            float lossb = ok ? (-ps / nvv) : 0.f;
            int ns = ok;
#pragma unroll
            for (int o = 16; o >= 1; o >>= 1) {
                lossb += __shfl_xor_sync(0xffffffffu, lossb, o);
                ns += __shfl_xor_sync(0xffffffffu, ns, o);
            }
            if (tid == 0) {
                out[0] = lossb / (float)(ns > 0 ? ns : 1);
                g_done = 0;
            }
        }
    }
}

// ---------------------------------------------------------------------------
extern "C" void kernel_launch(void* const* d_in, const int* in_sizes, int n_in,
                              void* d_out, int out_size) {
    const float* hid = (const float*)d_in[0];
    const float* W = (const float*)d_in[1];
    const float* bias = (const float*)d_in[2];
    const int* amask = (const int*)d_in[3];
    const int* labels = (const int*)d_in[4];
    float* out = (float*)d_out;

    cudaFuncSetAttribute(kern_proj, cudaFuncAttributeMaxDynamicSharedMemorySize, PROJ_SMEM);
    cudaFuncSetAttribute(kern_sim, cudaFuncAttributeMaxDynamicSharedMemorySize, SIM_SMEM);

    kern_wt<<<168, 256>>>(W);                                          // 0
    kern_proj<<<NROWS / 128, 256, PROJ_SMEM>>>(hid, bias, amask, labels); // 1
    kern_sim<<<BB * 36, 512, SIM_SMEM>>>(amask, labels);               // 2
    kern_loss<<<256, 128>>>(amask, labels, out);                       // 3
}